// round 16
// baseline (speedup 1.0000x reference)
#include <cuda_runtime.h>
#include <cuda_fp16.h>
#include <cstdint>

#define DI __device__ __forceinline__

// ---------------------------------------------------------------------------
// Problem constants
// ---------------------------------------------------------------------------
#define BATCH_  8192L
#define WTOT_   41943040L      // 4096*1024 + 4096*4096*2 + 1024*4096
#define HBUF_   33554432L      // 8192*4096

// GEMM tiling (R5/R11 configuration)
#define BM 256
#define BN 128
#define BK 32                      // halves per K-chunk
#define STAGES 4
#define THREADS 256
#define A_BYTES (BM * 128)         // 32768  (128B row = 64B hi | 64B lo)
#define B_BYTES (BN * 128)         // 16384
#define STAGE_BYTES (A_BYTES + B_BYTES)      // 49152
#define SMEM_BYTES (STAGES * STAGE_BYTES)    // 196608

// ---------------------------------------------------------------------------
// Scratch: __device__ globals (no runtime allocation anywhere)
// ---------------------------------------------------------------------------
__device__ __half g_Whi[WTOT_];
__device__ __half g_Wlo[WTOT_];
__device__ float  g_bias[4 * 4096];
__device__ __half g_hAhi[HBUF_], g_hAlo[HBUF_];
__device__ __half g_hBhi[HBUF_], g_hBlo[HBUF_];

// ---------------------------------------------------------------------------
// Small helpers
// ---------------------------------------------------------------------------
DI uint32_t smem_u32(const void* p) {
    uint32_t a;
    asm("{ .reg .u64 t; cvta.to.shared.u64 t, %1; cvt.u32.u64 %0, t; }"
        : "=r"(a) : "l"(p));
    return a;
}

DI void cp16(uint32_t dst, const void* src) {
    asm volatile("cp.async.cg.shared.global [%0], [%1], 16;"
                 :: "r"(dst), "l"(src));
}

DI void ldsm_x4(uint32_t* r, uint32_t addr) {
    asm volatile("ldmatrix.sync.aligned.m8n8.x4.shared.b16 {%0,%1,%2,%3}, [%4];"
                 : "=r"(r[0]), "=r"(r[1]), "=r"(r[2]), "=r"(r[3]) : "r"(addr));
}

// fp32-accumulator HMMA (main hh product)
DI void mma16816(float* d, const uint32_t* a, const uint32_t* b) {
    asm volatile(
        "mma.sync.aligned.m16n8k16.row.col.f32.f16.f16.f32 "
        "{%0,%1,%2,%3}, {%4,%5,%6,%7}, {%8,%9}, {%0,%1,%2,%3};"
        : "+f"(d[0]), "+f"(d[1]), "+f"(d[2]), "+f"(d[3])
        : "r"(a[0]), "r"(a[1]), "r"(a[2]), "r"(a[3]), "r"(b[0]), "r"(b[1]));
}

// fp16-accumulator HMMA (correction products hl / lh)
DI void mma_f16(uint32_t* d, const uint32_t* a, const uint32_t* b) {
    asm volatile(
        "mma.sync.aligned.m16n8k16.row.col.f16.f16.f16.f16 "
        "{%0,%1}, {%2,%3,%4,%5}, {%6,%7}, {%0,%1};"
        : "+r"(d[0]), "+r"(d[1])
        : "r"(a[0]), "r"(a[1]), "r"(a[2]), "r"(a[3]), "r"(b[0]), "r"(b[1]));
}

DI float softplus_f(float s) {
    return (s > 20.0f) ? s : log1pf(expf(s));
}

DI void split2(float v, __half& hi, __half& lo) {
    hi = __float2half_rn(v);
    lo = __float2half_rn(v - __half2float(hi));
}

// ---------------------------------------------------------------------------
// Prep: TWO launches total.
// ---------------------------------------------------------------------------
DI void prep_layer(const float* mw, const float* sw, const float* zw,
                   const float* mb, const float* sb, const float* zb,
                   long woff, long n, int layer, int dout,
                   long vb, long vgrid, int tid)
{
    long t = vb * 256 + tid;
    long stride = vgrid * 256;
    for (long e = t * 4; e < n; e += stride * 4) {
        float4 m = *(const float4*)(mw + e);
        float4 s = *(const float4*)(sw + e);
        float4 z = *(const float4*)(zw + e);
        float a0 = m.x + softplus_f(s.x) * z.x;
        float a1 = m.y + softplus_f(s.y) * z.y;
        float a2 = m.z + softplus_f(s.z) * z.z;
        float a3 = m.w + softplus_f(s.w) * z.w;
        __half h0, h1, h2, h3, l0, l1, l2, l3;
        split2(a0, h0, l0); split2(a1, h1, l1);
        split2(a2, h2, l2); split2(a3, h3, l3);
        __half2* ph = (__half2*)(g_Whi + woff + e);
        __half2* pl = (__half2*)(g_Wlo + woff + e);
        ph[0] = __halves2half2(h0, h1); ph[1] = __halves2half2(h2, h3);
        pl[0] = __halves2half2(l0, l1); pl[1] = __halves2half2(l2, l3);
    }
    if (t < dout)
        g_bias[layer * 4096 + t] = mb[t] + softplus_f(sb[t]) * zb[t];
}

DI void prep_x_part(const float* x, long n, long vb, long vgrid, int tid)
{
    long t = vb * 256 + tid;
    long stride = vgrid * 256;
    for (long e = t * 4; e < n; e += stride * 4) {
        float4 v = *(const float4*)(x + e);
        __half h0, h1, h2, h3, l0, l1, l2, l3;
        split2(v.x, h0, l0); split2(v.y, h1, l1);
        split2(v.z, h2, l2); split2(v.w, h3, l3);
        __half2* ph = (__half2*)(g_hAhi + e);
        __half2* pl = (__half2*)(g_hAlo + e);
        ph[0] = __halves2half2(h0, h1); ph[1] = __halves2half2(h2, h3);
        pl[0] = __halves2half2(l0, l1); pl[1] = __halves2half2(l2, l3);
    }
}

__global__ void prep_combo(
    const float* x, long nx, int xBlocks,
    const float* mwA, const float* swA, const float* zwA,
    const float* mbA, const float* sbA, const float* zbA,
    long woffA, long nA, int layerA, int doutA, int splitA,
    const float* mwB, const float* swB, const float* zwB,
    const float* mbB, const float* sbB, const float* zbB,
    long woffB, long nB, int layerB, int doutB)
{
    const int tid = threadIdx.x;
    const int b = (int)blockIdx.x;
    if (b < xBlocks) {
        prep_x_part(x, nx, (long)b, (long)xBlocks, tid);
    } else if (b < xBlocks + splitA) {
        prep_layer(mwA, swA, zwA, mbA, sbA, zbA, woffA, nA, layerA, doutA,
                   (long)(b - xBlocks), (long)splitA, tid);
    } else {
        prep_layer(mwB, swB, zwB, mbB, sbB, zbB, woffB, nB, layerB, doutB,
                   (long)(b - xBlocks - splitA),
                   (long)(gridDim.x - xBlocks - splitA), tid);
    }
}

// ---------------------------------------------------------------------------
// Stage loader — R5/R11 mapping; template flags skip unused lo planes.
// ---------------------------------------------------------------------------
template<int USE_ALO, int USE_BLO>
DI void load_stage(uint32_t stageBase, int K, long kc,
                   const __half* aHi, const __half* aLo,
                   const __half* bHi, const __half* bLo,
                   uint32_t aDst0, uint32_t bDst0)
{
    const long rstride = 64L * K;   // 64 rows forward, in halves
#pragma unroll
    for (int i2 = 0; i2 < 4; ++i2) {
        long so = kc + (long)i2 * rstride;
        uint32_t d = stageBase + aDst0 + (uint32_t)i2 * 8192u;
        cp16(d, aHi + so);
        if (USE_ALO) cp16(d ^ 64u, aLo + so);
        if (i2 < 2) {
            uint32_t db = stageBase + (uint32_t)A_BYTES + bDst0 + (uint32_t)i2 * 8192u;
            cp16(db, bHi + so);
            if (USE_BLO) cp16(db ^ 64u, bLo + so);
        }
    }
    asm volatile("cp.async.commit_group;" ::: "memory");
}

// ---------------------------------------------------------------------------
// Split-fp16 GEMM:  O[BM,BN] tile of  H[B,K] @ W[dout,K]^T + bias (+tanh)
// hh product -> fp32 accumulators.
// hl / lh correction products -> SHARED fp16 accumulator (cor), folded in
// the epilogue.  (R7 measured rel_err 9.05e-5 with this scheme -> safe.)
// <1,1>: hh + hl + lh   (layers 0, 1)
// <0,1>: hh + hl        (layer 2)
// <0,0>: hh             (layer 3)
// 8 warps as 4(m) x 2(n); warp tile 64x64; mma.sync m16n8k16, R11 pairing.
// ---------------------------------------------------------------------------
template<int USE_ALO, int USE_BLO>
__global__ void __launch_bounds__(THREADS, 1)
gemm_split(int inSel, long woff, int K, int dout, int bOff, int last,
           int storeLo, float* __restrict__ out)
{
    constexpr bool HAS_COR = (USE_ALO != 0) || (USE_BLO != 0);

    extern __shared__ __align__(128) uint8_t smem_raw[];
    const uint32_t sb = smem_u32(smem_raw);
    const int tid  = threadIdx.x;
    const int lane = tid & 31;
    const int wid  = tid >> 5;
    const int wm   = wid >> 1;      // 0..3
    const int wn   = wid & 1;       // 0..1

    const __half* Hhi = inSel ? g_hBhi : g_hAhi;
    const __half* Hlo = inSel ? g_hBlo : g_hAlo;
    __half* Ohi = inSel ? g_hAhi : g_hBhi;
    __half* Olo = inSel ? g_hAlo : g_hBlo;
    const __half* Whi = g_Whi + woff;
    const __half* Wlo = g_Wlo + woff;

    const long rowW = (long)blockIdx.x * BN;   // output-col base
    const long rowH = (long)blockIdx.y * BM;   // batch-row base

    // ---- loader thread mapping (R5) ----
    const int  lrow  = (tid & 7) + 8 * ((tid >> 5) & 7);  // 0..63
    const int  c4    = (tid >> 3) & 3;                    // 16B granule (hi)
    const uint32_t swzb = (uint32_t)((lrow & 7) << 4);
    const uint32_t aDst0 = (uint32_t)lrow * 128u + (((uint32_t)c4 * 16u) ^ swzb);
    const uint32_t bDst0 = aDst0;
    const __half* aSrcHi = Hhi + (rowH + lrow) * (long)K + c4 * 8;
    const __half* aSrcLo = Hlo + (rowH + lrow) * (long)K + c4 * 8;
    const __half* bSrcHi = Whi + (rowW + lrow) * (long)K + c4 * 8;
    const __half* bSrcLo = Wlo + (rowW + lrow) * (long)K + c4 * 8;

    // ---- ldmatrix per-lane address bases ----
    uint32_t aAddr[4];
#pragma unroll
    for (int mf = 0; mf < 4; ++mf) {
        uint32_t r = (uint32_t)(wm * 64 + mf * 16 + (lane & 15));
        uint32_t c = (uint32_t)((lane >> 4) << 4);
        aAddr[mf] = r * 128u + (c ^ ((r & 7u) << 4));
    }
    // B pair addresses (R11): pair p covers nf=2p,2p+1
    uint32_t bAddrP[4];
#pragma unroll
    for (int p = 0; p < 4; ++p) {
        uint32_t r = (uint32_t)(wn * 64 + p * 16 + ((lane >> 4) << 3) + (lane & 7));
        uint32_t c = (uint32_t)(((lane >> 3) & 1) << 4);
        bAddrP[p] = (uint32_t)A_BYTES + r * 128u + (c ^ ((r & 7u) << 4));
    }

    float acc[4][8][4];
    uint32_t cor[4][8][2];       // fp16x2 correction accumulators
#pragma unroll
    for (int mf = 0; mf < 4; ++mf)
#pragma unroll
        for (int nf = 0; nf < 8; ++nf) {
#pragma unroll
            for (int q = 0; q < 4; ++q) acc[mf][nf][q] = 0.0f;
            if (HAS_COR) { cor[mf][nf][0] = 0u; cor[mf][nf][1] = 0u; }
        }

    const int nIter = K / BK;

    load_stage<USE_ALO, USE_BLO>(sb + 0u * STAGE_BYTES, K, 0L * BK, aSrcHi, aSrcLo, bSrcHi, bSrcLo, aDst0, bDst0);
    load_stage<USE_ALO, USE_BLO>(sb + 1u * STAGE_BYTES, K, 1L * BK, aSrcHi, aSrcLo, bSrcHi, bSrcLo, aDst0, bDst0);
    load_stage<USE_ALO, USE_BLO>(sb + 2u * STAGE_BYTES, K, 2L * BK, aSrcHi, aSrcLo, bSrcHi, bSrcLo, aDst0, bDst0);

    for (int it = 0; it < nIter; ++it) {
        asm volatile("cp.async.wait_group 2;" ::: "memory");
        __syncthreads();

        if (it + 3 < nIter)
            load_stage<USE_ALO, USE_BLO>(sb + (uint32_t)((it + 3) & 3) * STAGE_BYTES, K, (long)(it + 3) * BK,
                                         aSrcHi, aSrcLo, bSrcHi, bSrcLo, aDst0, bDst0);
        else
            asm volatile("cp.async.commit_group;" ::: "memory");

        const uint32_t stg = sb + (uint32_t)(it & 3) * STAGE_BYTES;

#pragma unroll
        for (int kk = 0; kk < 2; ++kk) {
            const uint32_t kx = (uint32_t)kk * 32u;
            uint32_t ah[4][4], al[4][4];
#pragma unroll
            for (int mf = 0; mf < 4; ++mf) {
                ldsm_x4(ah[mf], stg + (aAddr[mf] ^ kx));
                if (USE_ALO) ldsm_x4(al[mf], stg + (aAddr[mf] ^ kx ^ 64u));
            }
#pragma unroll
            for (int p = 0; p < 4; ++p) {
                uint32_t bh[4], bl[4];
                ldsm_x4(bh, stg + (bAddrP[p] ^ kx));
                if (USE_BLO) ldsm_x4(bl, stg + (bAddrP[p] ^ kx ^ 64u));
#pragma unroll
                for (int mf = 0; mf < 4; ++mf) {
                    mma16816(acc[mf][2 * p + 0], ah[mf], bh + 0);
                    mma16816(acc[mf][2 * p + 1], ah[mf], bh + 2);
                }
                if (USE_BLO) {
#pragma unroll
                    for (int mf = 0; mf < 4; ++mf) {
                        mma_f16(cor[mf][2 * p + 0], ah[mf], bl + 0);
                        mma_f16(cor[mf][2 * p + 1], ah[mf], bl + 2);
                    }
                }
                if (USE_ALO) {
#pragma unroll
                    for (int mf = 0; mf < 4; ++mf) {
                        mma_f16(cor[mf][2 * p + 0], al[mf], bh + 0);
                        mma_f16(cor[mf][2 * p + 1], al[mf], bh + 2);
                    }
                }
            }
        }
    }

    asm volatile("cp.async.wait_group 0;" ::: "memory");

    // ---- epilogue: fold fp16 corrections, add bias, tanh / store ----
    const int r0 = lane >> 2;
    const int c0 = (lane & 3) * 2;
#pragma unroll
    for (int mf = 0; mf < 4; ++mf) {
#pragma unroll
        for (int nf = 0; nf < 8; ++nf) {
            const long col = rowW + wn * 64 + nf * 8 + c0;
            const float2 bv = *(const float2*)(g_bias + bOff + col);
#pragma unroll
            for (int h = 0; h < 2; ++h) {
                const long m = rowH + wm * 64 + mf * 16 + r0 + h * 8;
                float v0 = acc[mf][nf][h * 2 + 0] + bv.x;
                float v1 = acc[mf][nf][h * 2 + 1] + bv.y;
                if (HAS_COR) {
                    const float2 cf = __half22float2(
                        *reinterpret_cast<const __half2*>(&cor[mf][nf][h]));
                    v0 += cf.x;
                    v1 += cf.y;
                }
                if (last) {
                    *(float2*)(out + m * dout + col) = make_float2(v0, v1);
                } else {
                    v0 = tanhf(v0); v1 = tanhf(v1);
                    if (storeLo) {
                        __half h0, l0, h1, l1;
                        split2(v0, h0, l0); split2(v1, h1, l1);
                        *(__half2*)(Ohi + m * dout + col) = __halves2half2(h0, h1);
                        *(__half2*)(Olo + m * dout + col) = __halves2half2(l0, l1);
                    } else {
                        *(__half2*)(Ohi + m * dout + col) =
                            __halves2half2(__float2half_rn(v0), __float2half_rn(v1));
                    }
                }
            }
        }
    }
}

// ---------------------------------------------------------------------------
// Host launcher: 2 prep launches + 4 GEMMs  (launch #6 == L3 hh-only)
// products: L0 full(3), L1 full(3), L2 hh+hl(2), L3 hh(1)
// corrections (hl/lh) accumulate in fp16; hh in fp32.
// ---------------------------------------------------------------------------
extern "C" void kernel_launch(void* const* d_in, const int* in_sizes, int n_in,
                              void* d_out, int out_size)
{
    (void)in_sizes; (void)n_in; (void)out_size;

    static const int  DIN[4]   = {1024, 4096, 4096, 4096};
    static const int  DOUTL[4] = {4096, 4096, 4096, 1024};
    static const long WOFF[4]  = {0L, 4194304L, 20971520L, 37748736L};

    cudaFuncSetAttribute(gemm_split<1, 1>, cudaFuncAttributeMaxDynamicSharedMemorySize, SMEM_BYTES);
    cudaFuncSetAttribute(gemm_split<0, 1>, cudaFuncAttributeMaxDynamicSharedMemorySize, SMEM_BYTES);
    cudaFuncSetAttribute(gemm_split<0, 0>, cudaFuncAttributeMaxDynamicSharedMemorySize, SMEM_BYTES);

    const float* x = (const float*)d_in[0];

    prep_combo<<<2560, 256>>>(
        x, BATCH_ * 1024L, 512,
        (const float*)d_in[1],  (const float*)d_in[2],  (const float*)d_in[3],
        (const float*)d_in[4],  (const float*)d_in[5],  (const float*)d_in[6],
        WOFF[0], (long)DOUTL[0] * DIN[0], 0, DOUTL[0], 410,
        (const float*)d_in[7],  (const float*)d_in[8],  (const float*)d_in[9],
        (const float*)d_in[10], (const float*)d_in[11], (const float*)d_in[12],
        WOFF[1], (long)DOUTL[1] * DIN[1], 1, DOUTL[1]);

    prep_combo<<<2048, 256>>>(
        x, 0L, 0,
        (const float*)d_in[13], (const float*)d_in[14], (const float*)d_in[15],
        (const float*)d_in[16], (const float*)d_in[17], (const float*)d_in[18],
        WOFF[2], (long)DOUTL[2] * DIN[2], 2, DOUTL[2], 1638,
        (const float*)d_in[19], (const float*)d_in[20], (const float*)d_in[21],
        (const float*)d_in[22], (const float*)d_in[23], (const float*)d_in[24],
        WOFF[3], (long)DOUTL[3] * DIN[3], 3, DOUTL[3]);

    for (int j = 0; j < 4; ++j) {
        dim3 grid(DOUTL[j] / BN, (int)(BATCH_ / BM));
        const int last    = (j == 3) ? 1 : 0;
        const int storeLo = (j == 0) ? 1 : 0;
        if (j < 2)
            gemm_split<1, 1><<<grid, THREADS, SMEM_BYTES>>>(
                j & 1, WOFF[j], DIN[j], DOUTL[j], j * 4096, last, storeLo,
                (float*)d_out);
        else if (j == 2)
            gemm_split<0, 1><<<grid, THREADS, SMEM_BYTES>>>(
                j & 1, WOFF[j], DIN[j], DOUTL[j], j * 4096, last, storeLo,
                (float*)d_out);
        else
            gemm_split<0, 0><<<grid, THREADS, SMEM_BYTES>>>(
                j & 1, WOFF[j], DIN[j], DOUTL[j], j * 4096, last, storeLo,
                (float*)d_out);
    }
}

// round 17
// speedup vs baseline: 1.0180x; 1.0180x over previous
#include <cuda_runtime.h>
#include <cuda_fp16.h>
#include <cstdint>

#define DI __device__ __forceinline__

// ---------------------------------------------------------------------------
// Problem constants
// ---------------------------------------------------------------------------
#define BATCH_  8192L
#define WTOT_   41943040L      // 4096*1024 + 4096*4096*2 + 1024*4096
#define HBUF_   33554432L      // 8192*4096

// GEMM tiling (R5/R11 configuration)
#define BM 256
#define BN 128
#define BK 32                      // halves per K-chunk
#define STAGES 4
#define THREADS 256
#define A_BYTES (BM * 128)         // 32768  (128B row = 64B hi | 64B lo)
#define B_BYTES (BN * 128)         // 16384
#define STAGE_BYTES (A_BYTES + B_BYTES)      // 49152
#define SMEM_BYTES (STAGES * STAGE_BYTES)    // 196608

// ---------------------------------------------------------------------------
// Scratch: __device__ globals (no runtime allocation anywhere)
// ---------------------------------------------------------------------------
__device__ __half g_Whi[WTOT_];
__device__ __half g_Wlo[WTOT_];
__device__ float  g_bias[4 * 4096];
__device__ __half g_hAhi[HBUF_], g_hAlo[HBUF_];
__device__ __half g_hBhi[HBUF_], g_hBlo[HBUF_];

// ---------------------------------------------------------------------------
// Small helpers
// ---------------------------------------------------------------------------
DI uint32_t smem_u32(const void* p) {
    uint32_t a;
    asm("{ .reg .u64 t; cvta.to.shared.u64 t, %1; cvt.u32.u64 %0, t; }"
        : "=r"(a) : "l"(p));
    return a;
}

DI void cp16(uint32_t dst, const void* src) {
    asm volatile("cp.async.cg.shared.global [%0], [%1], 16;"
                 :: "r"(dst), "l"(src));
}

DI void ldsm_x4(uint32_t* r, uint32_t addr) {
    asm volatile("ldmatrix.sync.aligned.m8n8.x4.shared.b16 {%0,%1,%2,%3}, [%4];"
                 : "=r"(r[0]), "=r"(r[1]), "=r"(r[2]), "=r"(r[3]) : "r"(addr));
}

// fp32-accumulator HMMA
DI void mma16816(float* d, const uint32_t* a, const uint32_t* b) {
    asm volatile(
        "mma.sync.aligned.m16n8k16.row.col.f32.f16.f16.f32 "
        "{%0,%1,%2,%3}, {%4,%5,%6,%7}, {%8,%9}, {%0,%1,%2,%3};"
        : "+f"(d[0]), "+f"(d[1]), "+f"(d[2]), "+f"(d[3])
        : "r"(a[0]), "r"(a[1]), "r"(a[2]), "r"(a[3]), "r"(b[0]), "r"(b[1]));
}

// fp16-accumulator HMMA (correction products)
DI void mma_f16(uint32_t* d, const uint32_t* a, const uint32_t* b) {
    asm volatile(
        "mma.sync.aligned.m16n8k16.row.col.f16.f16.f16.f16 "
        "{%0,%1}, {%2,%3,%4,%5}, {%6,%7}, {%0,%1};"
        : "+r"(d[0]), "+r"(d[1])
        : "r"(a[0]), "r"(a[1]), "r"(a[2]), "r"(a[3]), "r"(b[0]), "r"(b[1]));
}

DI float softplus_f(float s) {
    return (s > 20.0f) ? s : log1pf(expf(s));
}

DI void split2(float v, __half& hi, __half& lo) {
    hi = __float2half_rn(v);
    lo = __float2half_rn(v - __half2float(hi));
}

// ---------------------------------------------------------------------------
// Prep: TWO launches total.
// ---------------------------------------------------------------------------
DI void prep_layer(const float* mw, const float* sw, const float* zw,
                   const float* mb, const float* sb, const float* zb,
                   long woff, long n, int layer, int dout,
                   long vb, long vgrid, int tid)
{
    long t = vb * 256 + tid;
    long stride = vgrid * 256;
    for (long e = t * 4; e < n; e += stride * 4) {
        float4 m = *(const float4*)(mw + e);
        float4 s = *(const float4*)(sw + e);
        float4 z = *(const float4*)(zw + e);
        float a0 = m.x + softplus_f(s.x) * z.x;
        float a1 = m.y + softplus_f(s.y) * z.y;
        float a2 = m.z + softplus_f(s.z) * z.z;
        float a3 = m.w + softplus_f(s.w) * z.w;
        __half h0, h1, h2, h3, l0, l1, l2, l3;
        split2(a0, h0, l0); split2(a1, h1, l1);
        split2(a2, h2, l2); split2(a3, h3, l3);
        __half2* ph = (__half2*)(g_Whi + woff + e);
        __half2* pl = (__half2*)(g_Wlo + woff + e);
        ph[0] = __halves2half2(h0, h1); ph[1] = __halves2half2(h2, h3);
        pl[0] = __halves2half2(l0, l1); pl[1] = __halves2half2(l2, l3);
    }
    if (t < dout)
        g_bias[layer * 4096 + t] = mb[t] + softplus_f(sb[t]) * zb[t];
}

DI void prep_x_part(const float* x, long n, long vb, long vgrid, int tid)
{
    long t = vb * 256 + tid;
    long stride = vgrid * 256;
    for (long e = t * 4; e < n; e += stride * 4) {
        float4 v = *(const float4*)(x + e);
        __half h0, h1, h2, h3, l0, l1, l2, l3;
        split2(v.x, h0, l0); split2(v.y, h1, l1);
        split2(v.z, h2, l2); split2(v.w, h3, l3);
        __half2* ph = (__half2*)(g_hAhi + e);
        __half2* pl = (__half2*)(g_hAlo + e);
        ph[0] = __halves2half2(h0, h1); ph[1] = __halves2half2(h2, h3);
        pl[0] = __halves2half2(l0, l1); pl[1] = __halves2half2(l2, l3);
    }
}

__global__ void prep_combo(
    const float* x, long nx, int xBlocks,
    const float* mwA, const float* swA, const float* zwA,
    const float* mbA, const float* sbA, const float* zbA,
    long woffA, long nA, int layerA, int doutA, int splitA,
    const float* mwB, const float* swB, const float* zwB,
    const float* mbB, const float* sbB, const float* zbB,
    long woffB, long nB, int layerB, int doutB)
{
    const int tid = threadIdx.x;
    const int b = (int)blockIdx.x;
    if (b < xBlocks) {
        prep_x_part(x, nx, (long)b, (long)xBlocks, tid);
    } else if (b < xBlocks + splitA) {
        prep_layer(mwA, swA, zwA, mbA, sbA, zbA, woffA, nA, layerA, doutA,
                   (long)(b - xBlocks), (long)splitA, tid);
    } else {
        prep_layer(mwB, swB, zwB, mbB, sbB, zbB, woffB, nB, layerB, doutB,
                   (long)(b - xBlocks - splitA),
                   (long)(gridDim.x - xBlocks - splitA), tid);
    }
}

// ---------------------------------------------------------------------------
// Stage loader — R5/R11 mapping; template flags skip unused lo planes.
// ---------------------------------------------------------------------------
template<int USE_ALO, int USE_BLO>
DI void load_stage(uint32_t stageBase, int K, long kc,
                   const __half* aHi, const __half* aLo,
                   const __half* bHi, const __half* bLo,
                   uint32_t aDst0, uint32_t bDst0)
{
    const long rstride = 64L * K;   // 64 rows forward, in halves
#pragma unroll
    for (int i2 = 0; i2 < 4; ++i2) {
        long so = kc + (long)i2 * rstride;
        uint32_t d = stageBase + aDst0 + (uint32_t)i2 * 8192u;
        cp16(d, aHi + so);
        if (USE_ALO) cp16(d ^ 64u, aLo + so);
        if (i2 < 2) {
            uint32_t db = stageBase + (uint32_t)A_BYTES + bDst0 + (uint32_t)i2 * 8192u;
            cp16(db, bHi + so);
            if (USE_BLO) cp16(db ^ 64u, bLo + so);
        }
    }
    asm volatile("cp.async.commit_group;" ::: "memory");
}

// ---------------------------------------------------------------------------
// Split-fp16 GEMM:  O[BM,BN] tile of  H[B,K] @ W[dout,K]^T + bias (+tanh)
// COR_F16 selects where hl/lh land:
//   COR_F16=0: corrections -> fp32 main accumulators (R15 proven, 250 regs)
//   COR_F16=1: corrections -> fp16 'cor' accumulators (rate experiment)
// Instantiations used:
//   <1,1,0>: layers 0,1 (full split, fp32 corrections -- no spill)
//   <0,1,1>: layer 2    (hh fp32 + hl fp16-acc -- fits: no al frags)
//   <0,0,0>: layer 3    (hh only)
// ---------------------------------------------------------------------------
template<int USE_ALO, int USE_BLO, int COR_F16>
__global__ void __launch_bounds__(THREADS, 1)
gemm_split(int inSel, long woff, int K, int dout, int bOff, int last,
           int storeLo, float* __restrict__ out)
{
    constexpr bool HAS_COR16 = COR_F16 && ((USE_ALO != 0) || (USE_BLO != 0));

    extern __shared__ __align__(128) uint8_t smem_raw[];
    const uint32_t sb = smem_u32(smem_raw);
    const int tid  = threadIdx.x;
    const int lane = tid & 31;
    const int wid  = tid >> 5;
    const int wm   = wid >> 1;      // 0..3
    const int wn   = wid & 1;       // 0..1

    const __half* Hhi = inSel ? g_hBhi : g_hAhi;
    const __half* Hlo = inSel ? g_hBlo : g_hAlo;
    __half* Ohi = inSel ? g_hAhi : g_hBhi;
    __half* Olo = inSel ? g_hAlo : g_hBlo;
    const __half* Whi = g_Whi + woff;
    const __half* Wlo = g_Wlo + woff;

    const long rowW = (long)blockIdx.x * BN;   // output-col base
    const long rowH = (long)blockIdx.y * BM;   // batch-row base

    // ---- loader thread mapping (R5) ----
    const int  lrow  = (tid & 7) + 8 * ((tid >> 5) & 7);  // 0..63
    const int  c4    = (tid >> 3) & 3;                    // 16B granule (hi)
    const uint32_t swzb = (uint32_t)((lrow & 7) << 4);
    const uint32_t aDst0 = (uint32_t)lrow * 128u + (((uint32_t)c4 * 16u) ^ swzb);
    const uint32_t bDst0 = aDst0;
    const __half* aSrcHi = Hhi + (rowH + lrow) * (long)K + c4 * 8;
    const __half* aSrcLo = Hlo + (rowH + lrow) * (long)K + c4 * 8;
    const __half* bSrcHi = Whi + (rowW + lrow) * (long)K + c4 * 8;
    const __half* bSrcLo = Wlo + (rowW + lrow) * (long)K + c4 * 8;

    // ---- ldmatrix per-lane address bases ----
    uint32_t aAddr[4];
#pragma unroll
    for (int mf = 0; mf < 4; ++mf) {
        uint32_t r = (uint32_t)(wm * 64 + mf * 16 + (lane & 15));
        uint32_t c = (uint32_t)((lane >> 4) << 4);
        aAddr[mf] = r * 128u + (c ^ ((r & 7u) << 4));
    }
    // B pair addresses (R11): pair p covers nf=2p,2p+1
    uint32_t bAddrP[4];
#pragma unroll
    for (int p = 0; p < 4; ++p) {
        uint32_t r = (uint32_t)(wn * 64 + p * 16 + ((lane >> 4) << 3) + (lane & 7));
        uint32_t c = (uint32_t)(((lane >> 3) & 1) << 4);
        bAddrP[p] = (uint32_t)A_BYTES + r * 128u + (c ^ ((r & 7u) << 4));
    }

    float acc[4][8][4];
    uint32_t cor[4][8][2];       // fp16x2 correction accumulators (COR_F16)
#pragma unroll
    for (int mf = 0; mf < 4; ++mf)
#pragma unroll
        for (int nf = 0; nf < 8; ++nf) {
#pragma unroll
            for (int q = 0; q < 4; ++q) acc[mf][nf][q] = 0.0f;
            if (HAS_COR16) { cor[mf][nf][0] = 0u; cor[mf][nf][1] = 0u; }
        }

    const int nIter = K / BK;

    load_stage<USE_ALO, USE_BLO>(sb + 0u * STAGE_BYTES, K, 0L * BK, aSrcHi, aSrcLo, bSrcHi, bSrcLo, aDst0, bDst0);
    load_stage<USE_ALO, USE_BLO>(sb + 1u * STAGE_BYTES, K, 1L * BK, aSrcHi, aSrcLo, bSrcHi, bSrcLo, aDst0, bDst0);
    load_stage<USE_ALO, USE_BLO>(sb + 2u * STAGE_BYTES, K, 2L * BK, aSrcHi, aSrcLo, bSrcHi, bSrcLo, aDst0, bDst0);

    for (int it = 0; it < nIter; ++it) {
        asm volatile("cp.async.wait_group 2;" ::: "memory");
        __syncthreads();

        if (it + 3 < nIter)
            load_stage<USE_ALO, USE_BLO>(sb + (uint32_t)((it + 3) & 3) * STAGE_BYTES, K, (long)(it + 3) * BK,
                                         aSrcHi, aSrcLo, bSrcHi, bSrcLo, aDst0, bDst0);
        else
            asm volatile("cp.async.commit_group;" ::: "memory");

        const uint32_t stg = sb + (uint32_t)(it & 3) * STAGE_BYTES;

#pragma unroll
        for (int kk = 0; kk < 2; ++kk) {
            const uint32_t kx = (uint32_t)kk * 32u;
            uint32_t ah[4][4], al[4][4];
#pragma unroll
            for (int mf = 0; mf < 4; ++mf) {
                ldsm_x4(ah[mf], stg + (aAddr[mf] ^ kx));
                if (USE_ALO) ldsm_x4(al[mf], stg + (aAddr[mf] ^ kx ^ 64u));
            }
#pragma unroll
            for (int p = 0; p < 4; ++p) {
                uint32_t bh[4], bl[4];
                ldsm_x4(bh, stg + (bAddrP[p] ^ kx));
                if (USE_BLO) ldsm_x4(bl, stg + (bAddrP[p] ^ kx ^ 64u));
#pragma unroll
                for (int mf = 0; mf < 4; ++mf) {
                    mma16816(acc[mf][2 * p + 0], ah[mf], bh + 0);
                    mma16816(acc[mf][2 * p + 1], ah[mf], bh + 2);
                }
                if (USE_BLO) {
                    if (COR_F16) {
#pragma unroll
                        for (int mf = 0; mf < 4; ++mf) {
                            mma_f16(cor[mf][2 * p + 0], ah[mf], bl + 0);
                            mma_f16(cor[mf][2 * p + 1], ah[mf], bl + 2);
                        }
                    } else {
#pragma unroll
                        for (int mf = 0; mf < 4; ++mf) {
                            mma16816(acc[mf][2 * p + 0], ah[mf], bl + 0);
                            mma16816(acc[mf][2 * p + 1], ah[mf], bl + 2);
                        }
                    }
                }
                if (USE_ALO) {
                    if (COR_F16) {
#pragma unroll
                        for (int mf = 0; mf < 4; ++mf) {
                            mma_f16(cor[mf][2 * p + 0], al[mf], bh + 0);
                            mma_f16(cor[mf][2 * p + 1], al[mf], bh + 2);
                        }
                    } else {
#pragma unroll
                        for (int mf = 0; mf < 4; ++mf) {
                            mma16816(acc[mf][2 * p + 0], al[mf], bh + 0);
                            mma16816(acc[mf][2 * p + 1], al[mf], bh + 2);
                        }
                    }
                }
            }
        }
    }

    asm volatile("cp.async.wait_group 0;" ::: "memory");

    // ---- epilogue: fold fp16 corrections (if any), add bias, tanh / store ----
    const int r0 = lane >> 2;
    const int c0 = (lane & 3) * 2;
#pragma unroll
    for (int mf = 0; mf < 4; ++mf) {
#pragma unroll
        for (int nf = 0; nf < 8; ++nf) {
            const long col = rowW + wn * 64 + nf * 8 + c0;
            const float2 bv = *(const float2*)(g_bias + bOff + col);
#pragma unroll
            for (int h = 0; h < 2; ++h) {
                const long m = rowH + wm * 64 + mf * 16 + r0 + h * 8;
                float v0 = acc[mf][nf][h * 2 + 0] + bv.x;
                float v1 = acc[mf][nf][h * 2 + 1] + bv.y;
                if (HAS_COR16) {
                    const float2 cf = __half22float2(
                        *reinterpret_cast<const __half2*>(&cor[mf][nf][h]));
                    v0 += cf.x;
                    v1 += cf.y;
                }
                if (last) {
                    *(float2*)(out + m * dout + col) = make_float2(v0, v1);
                } else {
                    v0 = tanhf(v0); v1 = tanhf(v1);
                    if (storeLo) {
                        __half h0, l0, h1, l1;
                        split2(v0, h0, l0); split2(v1, h1, l1);
                        *(__half2*)(Ohi + m * dout + col) = __halves2half2(h0, h1);
                        *(__half2*)(Olo + m * dout + col) = __halves2half2(l0, l1);
                    } else {
                        *(__half2*)(Ohi + m * dout + col) =
                            __halves2half2(__float2half_rn(v0), __float2half_rn(v1));
                    }
                }
            }
        }
    }
}

// ---------------------------------------------------------------------------
// Host launcher: 2 prep launches + 4 GEMMs
// L0/L1: <1,1,0>  fp32 corrections (R15 proven no-spill)
// L2:    <0,1,1>  hh fp32 + hl fp16-acc  (the rate experiment)
// L3:    <0,0,0>  hh only
// ---------------------------------------------------------------------------
extern "C" void kernel_launch(void* const* d_in, const int* in_sizes, int n_in,
                              void* d_out, int out_size)
{
    (void)in_sizes; (void)n_in; (void)out_size;

    static const int  DIN[4]   = {1024, 4096, 4096, 4096};
    static const int  DOUTL[4] = {4096, 4096, 4096, 1024};
    static const long WOFF[4]  = {0L, 4194304L, 20971520L, 37748736L};

    cudaFuncSetAttribute(gemm_split<1, 1, 0>, cudaFuncAttributeMaxDynamicSharedMemorySize, SMEM_BYTES);
    cudaFuncSetAttribute(gemm_split<0, 1, 1>, cudaFuncAttributeMaxDynamicSharedMemorySize, SMEM_BYTES);
    cudaFuncSetAttribute(gemm_split<0, 0, 0>, cudaFuncAttributeMaxDynamicSharedMemorySize, SMEM_BYTES);

    const float* x = (const float*)d_in[0];

    prep_combo<<<2560, 256>>>(
        x, BATCH_ * 1024L, 512,
        (const float*)d_in[1],  (const float*)d_in[2],  (const float*)d_in[3],
        (const float*)d_in[4],  (const float*)d_in[5],  (const float*)d_in[6],
        WOFF[0], (long)DOUTL[0] * DIN[0], 0, DOUTL[0], 410,
        (const float*)d_in[7],  (const float*)d_in[8],  (const float*)d_in[9],
        (const float*)d_in[10], (const float*)d_in[11], (const float*)d_in[12],
        WOFF[1], (long)DOUTL[1] * DIN[1], 1, DOUTL[1]);

    prep_combo<<<2048, 256>>>(
        x, 0L, 0,
        (const float*)d_in[13], (const float*)d_in[14], (const float*)d_in[15],
        (const float*)d_in[16], (const float*)d_in[17], (const float*)d_in[18],
        WOFF[2], (long)DOUTL[2] * DIN[2], 2, DOUTL[2], 1638,
        (const float*)d_in[19], (const float*)d_in[20], (const float*)d_in[21],
        (const float*)d_in[22], (const float*)d_in[23], (const float*)d_in[24],
        WOFF[3], (long)DOUTL[3] * DIN[3], 3, DOUTL[3]);

    for (int j = 0; j < 4; ++j) {
        dim3 grid(DOUTL[j] / BN, (int)(BATCH_ / BM));
        const int last    = (j == 3) ? 1 : 0;
        const int storeLo = (j == 0) ? 1 : 0;
        if (j < 2)
            gemm_split<1, 1, 0><<<grid, THREADS, SMEM_BYTES>>>(
                j & 1, WOFF[j], DIN[j], DOUTL[j], j * 4096, last, storeLo,
                (float*)d_out);
        else if (j == 2)
            gemm_split<0, 1, 1><<<grid, THREADS, SMEM_BYTES>>>(
                j & 1, WOFF[j], DIN[j], DOUTL[j], j * 4096, last, storeLo,
                (float*)d_out);
        else
            gemm_split<0, 0, 0><<<grid, THREADS, SMEM_BYTES>>>(
                j & 1, WOFF[j], DIN[j], DOUTL[j], j * 4096, last, storeLo,
                (float*)d_out);
    }
}